// round 15
// baseline (speedup 1.0000x reference)
#include <cuda_runtime.h>
#include <cuda_fp16.h>
#include <math.h>
#include <stdint.h>

#define N_NODES 50000
#define N_EDGES 800000
#define NGRAPH  64
#define NEG     0.01f
#define MTILES  391   // ceil(50000/128)
#define LDSW    72    // padded smem row stride (half) = 144B

// ---------------- device globals ----------------
__device__ float d_Hb[6400000];      // residual h (fp32)
__device__ float d_Gb[6400000];      // GRU state (fp32)
__device__ __half d_xh[6400000];     // x quantized
__device__ __half d_gh[6400000];     // g ping buffer
__device__ __half d_mh[6400000];     // g pong buffer (was mh)
__device__ __half d_hh[6400000];     // resid output
__device__ __half d_XWh[6400000];    // GCN xw (fp16, gathered)
// weight rows [n][k]: 0..127 Wgcn^T | 128+l*384 Wc[l]=Wgg[l]@WihT | 1280..1663 Whh | 1664..1791 W1^T
__device__ __half d_wh[229376];
__device__ float d_dinv[N_NODES];
__device__ float d_probs[N_NODES];
__device__ int d_degc[N_NODES];
__device__ int d_degr[N_NODES];
__device__ int d_fill[N_NODES];
__device__ int d_off[N_NODES + 1];
__device__ int d_csr[N_EDGES];
__device__ int d_bsum[256];

__device__ __forceinline__ float leaky(float x) { return x > 0.f ? x : NEG * x; }
__device__ __forceinline__ float sigm(float x)  { return 1.f / (1.f + __expf(-x)); }

__device__ __forceinline__ uint32_t smem_u32(const void* p) {
    uint32_t a;
    asm("{ .reg .u64 t; cvta.to.shared.u64 t, %1; cvt.u32.u64 %0, t; }" : "=r"(a) : "l"(p));
    return a;
}
__device__ __forceinline__ void cp16(uint32_t dst, const void* src, bool valid) {
    int sz = valid ? 16 : 0;
    asm volatile("cp.async.cg.shared.global [%0], [%1], 16, %2;"
                 :: "r"(dst), "l"(src), "r"(sz));
}
__device__ __forceinline__ void cp_commit() { asm volatile("cp.async.commit_group;"); }
__device__ __forceinline__ void ldmx4(uint32_t* r, uint32_t addr) {
    asm volatile("ldmatrix.sync.aligned.m8n8.x4.shared.b16 {%0,%1,%2,%3}, [%4];"
                 : "=r"(r[0]), "=r"(r[1]), "=r"(r[2]), "=r"(r[3]) : "r"(addr));
}
__device__ __forceinline__ void mma16816(float* c, const uint32_t* a, uint32_t b0, uint32_t b1) {
    asm volatile(
        "mma.sync.aligned.m16n8k16.row.col.f32.f16.f16.f32 "
        "{%0,%1,%2,%3}, {%4,%5,%6,%7}, {%8,%9}, {%0,%1,%2,%3};"
        : "+f"(c[0]), "+f"(c[1]), "+f"(c[2]), "+f"(c[3])
        : "r"(a[0]), "r"(a[1]), "r"(a[2]), "r"(a[3]), "r"(b0), "r"(b1));
}
__device__ __forceinline__ uint32_t pack4(float a, float b, float c, float d, uint32_t* hi) {
    __half2 h0 = __floats2half2_rn(a, b);
    __half2 h1 = __floats2half2_rn(c, d);
    *hi = *(uint32_t*)&h1;
    return *(uint32_t*)&h0;
}
__device__ __forceinline__ float4 h4tof4(uint2 p) {
    __half2 a = *(__half2*)&p.x, b = *(__half2*)&p.y;
    float2 fa = __half22float2(a), fb = __half22float2(b);
    return make_float4(fa.x, fa.y, fb.x, fb.y);
}

// ---------------- merged prep: quant_x | zero | wq ----------------
__global__ void k_prep(const float* __restrict__ x, const float* __restrict__ Wgcn,
                       const float* __restrict__ Whh, const float* __restrict__ W1,
                       float* __restrict__ out) {
    int b = blockIdx.x, tid = threadIdx.x;
    if (b < 6250) {
        long idx = (long)b * 256 + tid;
        if (idx < 1600000L) {
            float4 v = ((const float4*)x)[idx];
            uint32_t hi, lo = pack4(v.x, v.y, v.z, v.w, &hi);
            ((uint2*)d_xh)[idx] = make_uint2(lo, hi);
        }
    } else if (b < 6446) {
        int i = (b - 6250) * 256 + tid;
        if (i < N_NODES) { d_degc[i] = 0; d_degr[i] = 0; d_fill[i] = 0; }
        if (i < NGRAPH) out[i] = 0.f;
    } else {
        int idx = (b - 6446) * 256 + tid;
        if (idx < 640 * 128) {
            int r = idx >> 7, k = idx & 127;
            float v; long dr;
            if (r < 128)      { v = Wgcn[k * 128 + r];        dr = r; }
            else if (r < 512) { int n = r - 128; v = Whh[n * 128 + k]; dr = 1280 + n; }
            else              { int n = r - 512; v = W1[k * 128 + n];  dr = 1664 + n; }
            d_wh[dr * 128 + k] = __float2half_rn(v);
        }
    }
}
// Wc[l][j][n] = sum_c Wgg[l][j][c] * Wih[n][c]
__global__ void k_wc(const float* __restrict__ Wgg, const float* __restrict__ Wih) {
    int b = blockIdx.x;            // 0..1151
    int l = b / 384, n = b % 384;
    __shared__ float s[128];
    s[threadIdx.x] = Wih[n * 128 + threadIdx.x];
    __syncthreads();
    const float* wg = Wgg + (long)l * 16384 + threadIdx.x * 128;
    float acc = 0.f;
#pragma unroll 8
    for (int c = 0; c < 128; c++) acc += wg[c] * s[c];
    d_wh[(long)(128 + l * 384 + n) * 128 + threadIdx.x] = __float2half_rn(acc);
}

// ---------------- CSR build ----------------
__global__ void k_count(const int* __restrict__ row, const int* __restrict__ col) {
    int e = blockIdx.x * blockDim.x + threadIdx.x;
    if (e < N_EDGES) { atomicAdd(&d_degc[col[e]], 1); atomicAdd(&d_degr[row[e]], 1); }
}
__global__ void k_scan1() {     // + dinv
    __shared__ int sm[256];
    int i = blockIdx.x * 256 + threadIdx.x;
    int v = (i < N_NODES) ? d_degc[i] : 0;
    if (i < N_NODES) d_dinv[i] = rsqrtf((float)v + 1.f);
    sm[threadIdx.x] = v;
    __syncthreads();
    for (int o = 128; o; o >>= 1) {
        if (threadIdx.x < o) sm[threadIdx.x] += sm[threadIdx.x + o];
        __syncthreads();
    }
    if (threadIdx.x == 0) d_bsum[blockIdx.x] = sm[0];
}
__global__ void k_scan2() {
    __shared__ int sm[256];
    int t = threadIdx.x;
    int v = (t < 196) ? d_bsum[t] : 0;
    sm[t] = v; __syncthreads();
    for (int o = 1; o < 256; o <<= 1) {
        int x = (t >= o) ? sm[t - o] : 0;
        __syncthreads(); sm[t] += x; __syncthreads();
    }
    if (t < 196) d_bsum[t] = sm[t] - v;
    if (t == 0) d_off[N_NODES] = N_EDGES;
}
__global__ void k_scan3() {
    __shared__ int sm[256];
    int t = threadIdx.x, i = blockIdx.x * 256 + t;
    int v = (i < N_NODES) ? d_degc[i] : 0;
    sm[t] = v; __syncthreads();
    for (int o = 1; o < 256; o <<= 1) {
        int x = (t >= o) ? sm[t - o] : 0;
        __syncthreads(); sm[t] += x; __syncthreads();
    }
    if (i < N_NODES) d_off[i] = d_bsum[blockIdx.x] + sm[t] - v;
}
__global__ void k_scatter(const int* __restrict__ row, const int* __restrict__ col) {
    int e = blockIdx.x * blockDim.x + threadIdx.x;
    if (e < N_EDGES) {
        int c = col[e];
        d_csr[d_off[c] + atomicAdd(&d_fill[c], 1)] = row[e];
    }
}

// ---------------- fp16 HMMA GEMM, K=128 ----------------
// EPI 0: half out.  EPI 2: fused head -> probs (bias=b1, W2 in Cv, +b2, sigmoid).
template <int EPI>
__global__ void __launch_bounds__(256) k_mm(
    const __half* __restrict__ A, const __half* __restrict__ B,
    const float* __restrict__ bias, const float* __restrict__ b2,
    void* __restrict__ Cv)
{
    extern __shared__ __align__(16) char smraw[];
    __shared__ float srow[128];
    uint32_t smb = smem_u32(smraw);
    const int tid = threadIdx.x, lane = tid & 31, wid = tid >> 5;
    const int mw = (wid >> 1) * 32;
    const int nw = (wid & 1) * 64;
    const long m0 = (long)blockIdx.x * 128;

    if (EPI == 2) {
        if (tid < 128) srow[tid] = 0.f;
    }

    float acc[2][8][4];
#pragma unroll
    for (int i = 0; i < 2; i++)
#pragma unroll
        for (int j = 0; j < 8; j++)
#pragma unroll
            for (int e = 0; e < 4; e++) acc[i][j][e] = 0.f;

#define LOAD_STAGE(st, kc)                                                        \
    {                                                                             \
        uint32_t aA = smb + (st) * 36864;                                         \
        uint32_t aB = aA + 18432;                                                 \
        _Pragma("unroll")                                                         \
        for (int i_ = 0; i_ < 4; i_++) {                                          \
            int c_ = tid + i_ * 256;                                              \
            int row_ = c_ >> 3, col8_ = (c_ & 7) * 8;                             \
            long gr_ = m0 + row_;                                                 \
            bool v_ = gr_ < N_NODES;                                              \
            cp16(aA + (row_ * LDSW + col8_) * 2,                                  \
                 A + (v_ ? gr_ * 128 + (kc) + col8_ : 0), v_);                    \
            cp16(aB + (row_ * LDSW + col8_) * 2,                                  \
                 B + (long)row_ * 128 + (kc) + col8_, true);                      \
        }                                                                         \
        cp_commit();                                                              \
    }

    LOAD_STAGE(0, 0);
    const int arow = mw + (lane & 15);
    const int brow = nw + (lane & 15);
    const int acol = (lane >> 4) * 8;

#pragma unroll 1
    for (int ch = 0; ch < 2; ch++) {
        if (ch < 1) { LOAD_STAGE(1, 64); }
        if (ch < 1) asm volatile("cp.async.wait_group 1;");
        else        asm volatile("cp.async.wait_group 0;");
        __syncthreads();
        uint32_t sA = smb + (ch & 1) * 36864;
        uint32_t sB = sA + 18432;
#pragma unroll
        for (int ks = 0; ks < 4; ks++) {
            int k0 = ks * 16;
            uint32_t af[2][4];
#pragma unroll
            for (int i = 0; i < 2; i++)
                ldmx4(af[i], sA + ((arow + i * 16) * LDSW + k0 + acol) * 2);
#pragma unroll
            for (int j2 = 0; j2 < 4; j2++) {
                uint32_t t[4];
                ldmx4(t, sB + ((brow + j2 * 16) * LDSW + k0 + acol) * 2);
#pragma unroll
                for (int i = 0; i < 2; i++) {
                    mma16816(acc[i][2 * j2],     af[i], t[0], t[2]);
                    mma16816(acc[i][2 * j2 + 1], af[i], t[1], t[3]);
                }
            }
        }
        __syncthreads();
    }

    const int r_in = lane >> 2;
    const int cpair = (lane & 3) * 2;
    if (EPI == 0) {
#pragma unroll
        for (int i = 0; i < 2; i++) {
            long gm = m0 + mw + i * 16 + r_in;
#pragma unroll
            for (int j = 0; j < 8; j++) {
                int colg = nw + j * 8 + cpair;
                __half* C = (__half*)Cv;
                __half2 h0 = __floats2half2_rn(acc[i][j][0], acc[i][j][1]);
                __half2 h1 = __floats2half2_rn(acc[i][j][2], acc[i][j][3]);
                if (gm < N_NODES)     *(__half2*)&C[gm * 128 + colg] = h0;
                if (gm + 8 < N_NODES) *(__half2*)&C[(gm + 8) * 128 + colg] = h1;
            }
        }
    } else {
        const float* W2 = (const float*)Cv;
#pragma unroll
        for (int i = 0; i < 2; i++) {
            float p0 = 0.f, p1 = 0.f;
#pragma unroll
            for (int j = 0; j < 8; j++) {
                int colg = nw + j * 8 + cpair;
                float w0 = W2[colg], w1 = W2[colg + 1];
                float bx = bias[colg], by = bias[colg + 1];
                p0 += leaky(acc[i][j][0] + bx) * w0 + leaky(acc[i][j][1] + by) * w1;
                p1 += leaky(acc[i][j][2] + bx) * w0 + leaky(acc[i][j][3] + by) * w1;
            }
            atomicAdd(&srow[mw + i * 16 + r_in], p0);
            atomicAdd(&srow[mw + i * 16 + r_in + 8], p1);
        }
        __syncthreads();
        if (tid < 128) {
            long gm = m0 + tid;
            if (gm < N_NODES) d_probs[gm] = sigm(srow[tid] + b2[0]);
        }
    }
#undef LOAD_STAGE
}

// ---------------- fused layer: gather + gates GEMM + GRU ----------------
// smem: mA0 @0, mA1 @9216, gA0 @18432, gA1 @27648 (A tile for chunk t at t*9216),
//       B stages @36864 + st*55296. Total 147456 B.
// chunk 0,1: A = gathered m (smem), B = Wc[l];  chunk 2,3: A = gh_in own rows, B = Whh.
// Blocks: 0=r_sum, 1=z_sum, 2=i_n, 3=h_n. Epilogue: GRU -> Gb + gh_out.
__global__ void __launch_bounds__(512) k_layer(
    const __half* __restrict__ gh_in, __half* __restrict__ gh_out,
    const __half* __restrict__ wc, const __half* __restrict__ whh,
    const float* __restrict__ b_ih, const float* __restrict__ b_hh,
    float* __restrict__ Gb)
{
    extern __shared__ __align__(16) char smraw[];
    uint32_t smb = smem_u32(smraw);
    const int tid = threadIdx.x, lane = tid & 31, w = tid >> 5;
    const int mwarp = w & 1;
    const int nwarp = w >> 1;
    const long m0 = (long)blockIdx.x * 64;

#define GLOAD_B(st, c)                                                            \
    {                                                                             \
        const __half* Bs_ = ((c) < 2) ? wc : whh;                                 \
        int kc_ = ((c) & 1) * 64;                                                 \
        uint32_t aB = smb + 36864 + (st) * 55296;                                 \
        _Pragma("unroll")                                                         \
        for (int i_ = 0; i_ < 6; i_++) {                                          \
            int cc_ = tid + i_ * 512;                                             \
            int r_ = cc_ >> 3, c8_ = (cc_ & 7) * 8;                               \
            cp16(aB + (r_ * LDSW + c8_) * 2,                                      \
                 Bs_ + (long)r_ * 128 + kc_ + c8_, true);                         \
        }                                                                         \
        cp_commit();                                                              \
    }

    // gA tiles (gh_in own rows, chunks 2/3) — same commit group as B0
    {
#pragma unroll
        for (int i_ = 0; i_ < 2; i_++) {
            int idx = tid + i_ * 512;
            int r_ = idx >> 4, c8_ = (idx & 15) * 8;
            long gr_ = m0 + r_;
            bool v_ = gr_ < N_NODES;
            uint32_t tile = smb + ((c8_ < 64) ? 18432 : 27648);
            cp16(tile + (r_ * LDSW + (c8_ & 63)) * 2,
                 gh_in + (v_ ? gr_ * 128 + c8_ : 0), v_);
        }
    }
    GLOAD_B(0, 0);   // commits {gA, B0}

    // ---- gather phase: warp w handles rows w*4..w*4+3; lane covers cols lane*4 ----
    {
        const uint2* gin2 = (const uint2*)gh_in;
        char* mtile = smraw + ((lane < 16) ? 0 : 9216);
        int mcol = (lane * 4) & 63;
#pragma unroll 1
        for (int n = 0; n < 4; n++) {
            int r = w * 4 + n;
            long v = m0 + r;
            float a0 = 0.f, a1 = 0.f, a2 = 0.f, a3 = 0.f;
            if (v < N_NODES) {
                int s = d_off[v], e = d_off[v + 1];
                for (int i = s; i < e; i++) {
                    int u = d_csr[i];
                    float4 t = h4tof4(gin2[(long)u * 32 + lane]);
                    a0 += t.x; a1 += t.y; a2 += t.z; a3 += t.w;
                }
            }
            uint32_t hi, lo = pack4(a0, a1, a2, a3, &hi);
            *(uint2*)(mtile + (r * LDSW + mcol) * 2) = make_uint2(lo, hi);
        }
    }

    float acc[2][4][2][4];
#pragma unroll
    for (int i = 0; i < 2; i++)
#pragma unroll
        for (int b = 0; b < 4; b++)
#pragma unroll
            for (int j = 0; j < 2; j++)
#pragma unroll
                for (int e = 0; e < 4; e++) acc[i][b][j][e] = 0.f;

    const int arow = mwarp * 32 + (lane & 15);
    const int brow = nwarp * 16 + (lane & 15);
    const int acol = (lane >> 4) * 8;

#pragma unroll 1
    for (int t = 0; t < 4; t++) {
        if (t < 3) { GLOAD_B((t + 1) & 1, t + 1); }
        if (t < 3) asm volatile("cp.async.wait_group 1;");
        else       asm volatile("cp.async.wait_group 0;");
        __syncthreads();
        int ph = t >> 1;
        uint32_t sA = smb + t * 9216;
        uint32_t sB = smb + 36864 + (t & 1) * 55296;
#pragma unroll
        for (int ks = 0; ks < 4; ks++) {
            int k0 = ks * 16;
            uint32_t af[2][4];
#pragma unroll
            for (int i = 0; i < 2; i++)
                ldmx4(af[i], sA + ((arow + i * 16) * LDSW + k0 + acol) * 2);
#pragma unroll
            for (int sb = 0; sb < 3; sb++) {
                const int lb = (ph == 0) ? sb : (sb == 2 ? 3 : sb);
                uint32_t bt[4];
                ldmx4(bt, sB + ((sb * 128 + brow) * LDSW + k0 + acol) * 2);
#pragma unroll
                for (int i = 0; i < 2; i++) {
                    mma16816(acc[i][lb][0], af[i], bt[0], bt[2]);
                    mma16816(acc[i][lb][1], af[i], bt[1], bt[3]);
                }
            }
        }
        __syncthreads();
    }

    const int r_in = lane >> 2;
    const int cpair = (lane & 3) * 2;
#pragma unroll
    for (int i = 0; i < 2; i++) {
#pragma unroll
        for (int hrow = 0; hrow < 2; hrow++) {
            long gm = m0 + mwarp * 32 + i * 16 + r_in + hrow * 8;
            if (gm >= N_NODES) continue;
#pragma unroll
            for (int j = 0; j < 2; j++) {
                int c = nwarp * 16 + j * 8 + cpair;
                float g2[2];
#pragma unroll
                for (int e = 0; e < 2; e++) {
                    int cc = c + e;
                    float rs = acc[i][0][j][hrow * 2 + e] + b_ih[cc] + b_hh[cc];
                    float zs = acc[i][1][j][hrow * 2 + e] + b_ih[128 + cc] + b_hh[128 + cc];
                    float in_ = acc[i][2][j][hrow * 2 + e] + b_ih[256 + cc];
                    float hn  = acc[i][3][j][hrow * 2 + e] + b_hh[256 + cc];
                    float r = sigm(rs), z = sigm(zs);
                    float n = tanhf(in_ + r * hn);
                    g2[e] = (1.f - z) * n + z * Gb[gm * 128 + cc];
                }
                *(float2*)&Gb[gm * 128 + c] = make_float2(g2[0], g2[1]);
                *(__half2*)&gh_out[gm * 128 + c] = __floats2half2_rn(g2[0], g2[1]);
            }
        }
    }
#undef GLOAD_B
}

// ---------------- GCN aggregation (pull-CSR, warp/node) ----------------
__global__ void k_gcn_agg(const float* __restrict__ bias) {
    int v = blockIdx.x * 8 + (threadIdx.x >> 5);
    if (v >= N_NODES) return;
    int lane = threadIdx.x & 31;
    const uint2* x2 = (const uint2*)d_XWh;
    float4 acc = make_float4(0.f, 0.f, 0.f, 0.f);
    float dv = d_dinv[v];
    int s = d_off[v], e = d_off[v + 1];
    for (int i = s; i < e; i++) {
        int u = d_csr[i];
        float c = d_dinv[u] * dv;
        float4 t = h4tof4(x2[(long)u * 32 + lane]);
        acc.x += t.x * c; acc.y += t.y * c; acc.z += t.z * c; acc.w += t.w * c;
    }
    float4 slf = h4tof4(x2[(long)v * 32 + lane]);
    float sc = dv * dv;
    float4 b = ((const float4*)bias)[lane];
    acc.x = leaky(acc.x + slf.x * sc + b.x);
    acc.y = leaky(acc.y + slf.y * sc + b.y);
    acc.z = leaky(acc.z + slf.z * sc + b.z);
    acc.w = leaky(acc.w + slf.w * sc + b.w);
    ((float4*)d_Hb)[(long)v * 32 + lane] = acc;
    ((float4*)d_Gb)[(long)v * 32 + lane] = acc;
    uint32_t hi, lo = pack4(acc.x, acc.y, acc.z, acc.w, &hi);
    ((uint2*)d_gh)[(long)v * 32 + lane] = make_uint2(lo, hi);
}

// ---------------- elementwise ----------------
__global__ void k_resid() {
    long idx = (long)blockIdx.x * 256 + threadIdx.x;
    if (idx >= 1600000L) return;
    float4 g = ((const float4*)d_Gb)[idx];
    float4 hh = ((const float4*)d_Hb)[idx];
    uint32_t hi, lo = pack4(leaky(g.x) + hh.x, leaky(g.y) + hh.y,
                            leaky(g.z) + hh.z, leaky(g.w) + hh.w, &hi);
    ((uint2*)d_hh)[idx] = make_uint2(lo, hi);
}

// ---------------- merged loss ----------------
__global__ void k_loss(const int* __restrict__ row, const int* __restrict__ col,
                       const int* __restrict__ batch, float* __restrict__ out) {
    __shared__ float sm[NGRAPH];
    if (threadIdx.x < NGRAPH) sm[threadIdx.x] = 0.f;
    __syncthreads();
    if (blockIdx.x < 512) {
        for (int v = blockIdx.x * 256 + threadIdx.x; v < N_NODES; v += 512 * 256)
            atomicAdd(&sm[batch[v]], -0.5f * d_probs[v] * (float)d_degr[v]);
    } else {
        for (int e = (blockIdx.x - 512) * 256 + threadIdx.x; e < N_EDGES; e += 512 * 256) {
            int r = row[e];
            atomicAdd(&sm[batch[r]], 0.5f * d_probs[r] * d_probs[col[e]]);
        }
    }
    __syncthreads();
    if (threadIdx.x < NGRAPH) atomicAdd(&out[threadIdx.x], sm[threadIdx.x]);
}

// ---------------- launch ----------------
extern "C" void kernel_launch(void* const* d_in, const int* in_sizes, int n_in,
                              void* d_out, int out_size)
{
    const float* x     = (const float*)d_in[0];
    const int*   ei    = (const int*)d_in[1];
    const int*   batch = (const int*)d_in[2];
    const float* W_gcn = (const float*)d_in[3];
    const float* b_gcn = (const float*)d_in[4];
    const float* W_gg  = (const float*)d_in[5];
    const float* W_ih  = (const float*)d_in[6];
    const float* W_hh  = (const float*)d_in[7];
    const float* b_ih  = (const float*)d_in[8];
    const float* b_hh  = (const float*)d_in[9];
    const float* W1    = (const float*)d_in[10];
    const float* b1    = (const float*)d_in[11];
    const float* W2    = (const float*)d_in[12];
    const float* b2    = (const float*)d_in[13];
    float* out = (float*)d_out;
    const int* row = ei;
    const int* col = ei + N_EDGES;

    const int SMEM = 2 * 36864;     // k_mm double buffer
    const int SML  = 147456;        // k_layer: 4 A tiles + 2 B stages (144 KB)
    cudaFuncSetAttribute(k_mm<0>, cudaFuncAttributeMaxDynamicSharedMemorySize, SMEM);
    cudaFuncSetAttribute(k_mm<2>, cudaFuncAttributeMaxDynamicSharedMemorySize, SMEM);
    cudaFuncSetAttribute(k_layer, cudaFuncAttributeMaxDynamicSharedMemorySize, SML);

    __half *xh, *gh, *mh, *hh, *wh, *XWh;
    float *Gb;
    cudaGetSymbolAddress((void**)&xh, d_xh);
    cudaGetSymbolAddress((void**)&gh, d_gh);
    cudaGetSymbolAddress((void**)&mh, d_mh);
    cudaGetSymbolAddress((void**)&hh, d_hh);
    cudaGetSymbolAddress((void**)&wh, d_wh);
    cudaGetSymbolAddress((void**)&XWh, d_XWh);
    cudaGetSymbolAddress((void**)&Gb, d_Gb);

    // prep + CSR build
    k_prep<<<6766, 256>>>(x, W_gcn, W_hh, W1, out);
    k_count<<<3125, 256>>>(row, col);
    k_wc<<<1152, 128>>>(W_gg, W_ih);
    k_scan1<<<196, 256>>>();
    k_scan2<<<1, 256>>>();
    k_scan3<<<196, 256>>>();
    k_scatter<<<3125, 256>>>(row, col);

    // GCN
    k_mm<0><<<MTILES, 256, SMEM>>>(xh, wh, nullptr, nullptr, XWh);
    k_gcn_agg<<<6250, 256>>>(b_gcn);

    // 3x fused GatedGraphConv layers (gather + gates GEMM + GRU), gh ping-pong
    __half* ghb[2] = {gh, mh};
    for (int l = 0; l < 3; l++) {
        k_layer<<<782, 512, SML>>>(ghb[l & 1], ghb[(l + 1) & 1],
                                   wh + (long)(128 + l * 384) * 128,
                                   wh + 1280L * 128, b_ih, b_hh, Gb);
    }

    // head (GEMM + W1/b1 + leaky + W2/b2 + sigmoid fused -> d_probs)
    k_resid<<<6250, 256>>>();
    k_mm<2><<<MTILES, 256, SMEM>>>(hh, wh + 1664L * 128, b1, b2, (void*)W2);

    // loss
    k_loss<<<1024, 256>>>(row, col, batch, out);
}

// round 16
// speedup vs baseline: 1.1671x; 1.1671x over previous
#include <cuda_runtime.h>
#include <cuda_fp16.h>
#include <math.h>
#include <stdint.h>

#define N_NODES 50000
#define N_EDGES 800000
#define NGRAPH  64
#define NEG     0.01f
#define MTILES  391   // ceil(50000/128)
#define LDSW    72    // padded smem row stride (half) = 144B

// ---------------- device globals ----------------
__device__ __half d_Hbh[6400000];    // residual h (fp16)
__device__ __half d_xh[6400000];     // x quantized
__device__ __half d_gh[6400000];     // g state (fp16, in-place per layer)
__device__ __half d_mh[6400000];     // aggregated message
__device__ __half d_hh[6400000];     // resid output (head GEMM A)
__device__ __half d_XWh[6400000];    // GCN xw (fp16, gathered)
// weight rows [n][k]: 0..127 Wgcn^T | 128+l*384 Wc[l]=Wgg[l]@WihT | 1280..1663 Whh | 1664..1791 W1^T
__device__ __half d_wh[229376];
__device__ float d_dinv[N_NODES];
__device__ float d_probs[N_NODES];
__device__ int d_degc[N_NODES];
__device__ int d_degr[N_NODES];
__device__ int d_fill[N_NODES];
__device__ int d_off[N_NODES + 1];
__device__ int d_csr[N_EDGES];
__device__ int d_bsum[256];

__device__ __forceinline__ float leaky(float x) { return x > 0.f ? x : NEG * x; }
__device__ __forceinline__ float sigm(float x)  { return 1.f / (1.f + __expf(-x)); }

__device__ __forceinline__ uint32_t smem_u32(const void* p) {
    uint32_t a;
    asm("{ .reg .u64 t; cvta.to.shared.u64 t, %1; cvt.u32.u64 %0, t; }" : "=r"(a) : "l"(p));
    return a;
}
__device__ __forceinline__ void cp16(uint32_t dst, const void* src, bool valid) {
    int sz = valid ? 16 : 0;
    asm volatile("cp.async.cg.shared.global [%0], [%1], 16, %2;"
                 :: "r"(dst), "l"(src), "r"(sz));
}
__device__ __forceinline__ void cp_commit() { asm volatile("cp.async.commit_group;"); }
__device__ __forceinline__ void ldmx4(uint32_t* r, uint32_t addr) {
    asm volatile("ldmatrix.sync.aligned.m8n8.x4.shared.b16 {%0,%1,%2,%3}, [%4];"
                 : "=r"(r[0]), "=r"(r[1]), "=r"(r[2]), "=r"(r[3]) : "r"(addr));
}
__device__ __forceinline__ void mma16816(float* c, const uint32_t* a, uint32_t b0, uint32_t b1) {
    asm volatile(
        "mma.sync.aligned.m16n8k16.row.col.f32.f16.f16.f32 "
        "{%0,%1,%2,%3}, {%4,%5,%6,%7}, {%8,%9}, {%0,%1,%2,%3};"
        : "+f"(c[0]), "+f"(c[1]), "+f"(c[2]), "+f"(c[3])
        : "r"(a[0]), "r"(a[1]), "r"(a[2]), "r"(a[3]), "r"(b0), "r"(b1));
}
__device__ __forceinline__ uint32_t pack4(float a, float b, float c, float d, uint32_t* hi) {
    __half2 h0 = __floats2half2_rn(a, b);
    __half2 h1 = __floats2half2_rn(c, d);
    *hi = *(uint32_t*)&h1;
    return *(uint32_t*)&h0;
}
__device__ __forceinline__ float4 h4tof4(uint2 p) {
    __half2 a = *(__half2*)&p.x, b = *(__half2*)&p.y;
    float2 fa = __half22float2(a), fb = __half22float2(b);
    return make_float4(fa.x, fa.y, fb.x, fb.y);
}

// ---------------- merged prep: quant_x | zero | wq ----------------
__global__ void k_prep(const float* __restrict__ x, const float* __restrict__ Wgcn,
                       const float* __restrict__ Whh, const float* __restrict__ W1,
                       float* __restrict__ out) {
    int b = blockIdx.x, tid = threadIdx.x;
    if (b < 6250) {
        long idx = (long)b * 256 + tid;
        if (idx < 1600000L) {
            float4 v = ((const float4*)x)[idx];
            uint32_t hi, lo = pack4(v.x, v.y, v.z, v.w, &hi);
            ((uint2*)d_xh)[idx] = make_uint2(lo, hi);
        }
    } else if (b < 6446) {
        int i = (b - 6250) * 256 + tid;
        if (i < N_NODES) { d_degc[i] = 0; d_degr[i] = 0; d_fill[i] = 0; }
        if (i < NGRAPH) out[i] = 0.f;
    } else {
        int idx = (b - 6446) * 256 + tid;
        if (idx < 640 * 128) {
            int r = idx >> 7, k = idx & 127;
            float v; long dr;
            if (r < 128)      { v = Wgcn[k * 128 + r];        dr = r; }
            else if (r < 512) { int n = r - 128; v = Whh[n * 128 + k]; dr = 1280 + n; }
            else              { int n = r - 512; v = W1[k * 128 + n];  dr = 1664 + n; }
            d_wh[dr * 128 + k] = __float2half_rn(v);
        }
    }
}
// Wc[l][j][n] = sum_c Wgg[l][j][c] * Wih[n][c]
__global__ void k_wc(const float* __restrict__ Wgg, const float* __restrict__ Wih) {
    int b = blockIdx.x;            // 0..1151
    int l = b / 384, n = b % 384;
    __shared__ float s[128];
    s[threadIdx.x] = Wih[n * 128 + threadIdx.x];
    __syncthreads();
    const float* wg = Wgg + (long)l * 16384 + threadIdx.x * 128;
    float acc = 0.f;
#pragma unroll 8
    for (int c = 0; c < 128; c++) acc += wg[c] * s[c];
    d_wh[(long)(128 + l * 384 + n) * 128 + threadIdx.x] = __float2half_rn(acc);
}

// ---------------- CSR build ----------------
__global__ void k_count(const int* __restrict__ row, const int* __restrict__ col) {
    int e = blockIdx.x * blockDim.x + threadIdx.x;
    if (e < N_EDGES) { atomicAdd(&d_degc[col[e]], 1); atomicAdd(&d_degr[row[e]], 1); }
}
__global__ void k_scan1() {     // + dinv
    __shared__ int sm[256];
    int i = blockIdx.x * 256 + threadIdx.x;
    int v = (i < N_NODES) ? d_degc[i] : 0;
    if (i < N_NODES) d_dinv[i] = rsqrtf((float)v + 1.f);
    sm[threadIdx.x] = v;
    __syncthreads();
    for (int o = 128; o; o >>= 1) {
        if (threadIdx.x < o) sm[threadIdx.x] += sm[threadIdx.x + o];
        __syncthreads();
    }
    if (threadIdx.x == 0) d_bsum[blockIdx.x] = sm[0];
}
__global__ void k_scan2() {
    __shared__ int sm[256];
    int t = threadIdx.x;
    int v = (t < 196) ? d_bsum[t] : 0;
    sm[t] = v; __syncthreads();
    for (int o = 1; o < 256; o <<= 1) {
        int x = (t >= o) ? sm[t - o] : 0;
        __syncthreads(); sm[t] += x; __syncthreads();
    }
    if (t < 196) d_bsum[t] = sm[t] - v;
    if (t == 0) d_off[N_NODES] = N_EDGES;
}
__global__ void k_scan3() {
    __shared__ int sm[256];
    int t = threadIdx.x, i = blockIdx.x * 256 + t;
    int v = (i < N_NODES) ? d_degc[i] : 0;
    sm[t] = v; __syncthreads();
    for (int o = 1; o < 256; o <<= 1) {
        int x = (t >= o) ? sm[t - o] : 0;
        __syncthreads(); sm[t] += x; __syncthreads();
    }
    if (i < N_NODES) d_off[i] = d_bsum[blockIdx.x] + sm[t] - v;
}
__global__ void k_scatter(const int* __restrict__ row, const int* __restrict__ col) {
    int e = blockIdx.x * blockDim.x + threadIdx.x;
    if (e < N_EDGES) {
        int c = col[e];
        d_csr[d_off[c] + atomicAdd(&d_fill[c], 1)] = row[e];
    }
}

// ---------------- fp16 HMMA GEMM, K=128 ----------------
// EPI 0: half out.  EPI 2: fused head -> probs (bias=b1, W2 in Cv, +b2, sigmoid).
template <int EPI>
__global__ void __launch_bounds__(256) k_mm(
    const __half* __restrict__ A, const __half* __restrict__ B,
    const float* __restrict__ bias, const float* __restrict__ b2,
    void* __restrict__ Cv)
{
    extern __shared__ __align__(16) char smraw[];
    __shared__ float srow[128];
    uint32_t smb = smem_u32(smraw);
    const int tid = threadIdx.x, lane = tid & 31, wid = tid >> 5;
    const int mw = (wid >> 1) * 32;
    const int nw = (wid & 1) * 64;
    const long m0 = (long)blockIdx.x * 128;

    if (EPI == 2) {
        if (tid < 128) srow[tid] = 0.f;
    }

    float acc[2][8][4];
#pragma unroll
    for (int i = 0; i < 2; i++)
#pragma unroll
        for (int j = 0; j < 8; j++)
#pragma unroll
            for (int e = 0; e < 4; e++) acc[i][j][e] = 0.f;

#define LOAD_STAGE(st, kc)                                                        \
    {                                                                             \
        uint32_t aA = smb + (st) * 36864;                                         \
        uint32_t aB = aA + 18432;                                                 \
        _Pragma("unroll")                                                         \
        for (int i_ = 0; i_ < 4; i_++) {                                          \
            int c_ = tid + i_ * 256;                                              \
            int row_ = c_ >> 3, col8_ = (c_ & 7) * 8;                             \
            long gr_ = m0 + row_;                                                 \
            bool v_ = gr_ < N_NODES;                                              \
            cp16(aA + (row_ * LDSW + col8_) * 2,                                  \
                 A + (v_ ? gr_ * 128 + (kc) + col8_ : 0), v_);                    \
            cp16(aB + (row_ * LDSW + col8_) * 2,                                  \
                 B + (long)row_ * 128 + (kc) + col8_, true);                      \
        }                                                                         \
        cp_commit();                                                              \
    }

    LOAD_STAGE(0, 0);
    const int arow = mw + (lane & 15);
    const int brow = nw + (lane & 15);
    const int acol = (lane >> 4) * 8;

#pragma unroll 1
    for (int ch = 0; ch < 2; ch++) {
        if (ch < 1) { LOAD_STAGE(1, 64); }
        if (ch < 1) asm volatile("cp.async.wait_group 1;");
        else        asm volatile("cp.async.wait_group 0;");
        __syncthreads();
        uint32_t sA = smb + (ch & 1) * 36864;
        uint32_t sB = sA + 18432;
#pragma unroll
        for (int ks = 0; ks < 4; ks++) {
            int k0 = ks * 16;
            uint32_t af[2][4];
#pragma unroll
            for (int i = 0; i < 2; i++)
                ldmx4(af[i], sA + ((arow + i * 16) * LDSW + k0 + acol) * 2);
#pragma unroll
            for (int j2 = 0; j2 < 4; j2++) {
                uint32_t t[4];
                ldmx4(t, sB + ((brow + j2 * 16) * LDSW + k0 + acol) * 2);
#pragma unroll
                for (int i = 0; i < 2; i++) {
                    mma16816(acc[i][2 * j2],     af[i], t[0], t[2]);
                    mma16816(acc[i][2 * j2 + 1], af[i], t[1], t[3]);
                }
            }
        }
        __syncthreads();
    }

    const int r_in = lane >> 2;
    const int cpair = (lane & 3) * 2;
    if (EPI == 0) {
#pragma unroll
        for (int i = 0; i < 2; i++) {
            long gm = m0 + mw + i * 16 + r_in;
#pragma unroll
            for (int j = 0; j < 8; j++) {
                int colg = nw + j * 8 + cpair;
                __half* C = (__half*)Cv;
                __half2 h0 = __floats2half2_rn(acc[i][j][0], acc[i][j][1]);
                __half2 h1 = __floats2half2_rn(acc[i][j][2], acc[i][j][3]);
                if (gm < N_NODES)     *(__half2*)&C[gm * 128 + colg] = h0;
                if (gm + 8 < N_NODES) *(__half2*)&C[(gm + 8) * 128 + colg] = h1;
            }
        }
    } else {
        const float* W2 = (const float*)Cv;
#pragma unroll
        for (int i = 0; i < 2; i++) {
            float p0 = 0.f, p1 = 0.f;
#pragma unroll
            for (int j = 0; j < 8; j++) {
                int colg = nw + j * 8 + cpair;
                float w0 = W2[colg], w1 = W2[colg + 1];
                float bx = bias[colg], by = bias[colg + 1];
                p0 += leaky(acc[i][j][0] + bx) * w0 + leaky(acc[i][j][1] + by) * w1;
                p1 += leaky(acc[i][j][2] + bx) * w0 + leaky(acc[i][j][3] + by) * w1;
            }
            atomicAdd(&srow[mw + i * 16 + r_in], p0);
            atomicAdd(&srow[mw + i * 16 + r_in + 8], p1);
        }
        __syncthreads();
        if (tid < 128) {
            long gm = m0 + tid;
            if (gm < N_NODES) d_probs[gm] = sigm(srow[tid] + b2[0]);
        }
    }
#undef LOAD_STAGE
}

// ---------------- fused gates GEMM + GRU (2-stage; h read from live smem A-tiles) ----------------
// Blocks: 0=r_sum, 1=z_sum, 2=i_n, 3=h_n.
// chunks 0-1: A=mh, B=Wc[l] -> {0,1,2};  chunks 2-3: A=gh, B=Whh -> {0,1,3}
// After the loop: stage0 A-tile = gh cols 0-63, stage1 A-tile = gh cols 64-127.
__global__ void __launch_bounds__(512) k_gates(
    const __half* __restrict__ mh, __half* gh,
    const __half* __restrict__ wc, const __half* __restrict__ whh,
    const float* __restrict__ b_ih, const float* __restrict__ b_hh)
{
    extern __shared__ __align__(16) char smraw[];
    uint32_t smb = smem_u32(smraw);
    const int tid = threadIdx.x, lane = tid & 31, w = tid >> 5;
    const int mwarp = w & 1;
    const int nwarp = w >> 1;
    const long m0 = (long)blockIdx.x * 64;

    float acc[2][4][2][4];
#pragma unroll
    for (int i = 0; i < 2; i++)
#pragma unroll
        for (int b = 0; b < 4; b++)
#pragma unroll
            for (int j = 0; j < 2; j++)
#pragma unroll
                for (int e = 0; e < 4; e++) acc[i][b][j][e] = 0.f;

#define GLOAD(st, c)                                                              \
    {                                                                             \
        int p_ = (c) >> 1, kc_ = ((c) & 1) * 64;                                  \
        const __half* As_ = p_ ? gh : mh;                                         \
        const __half* Bs_ = p_ ? whh : wc;                                        \
        uint32_t aA = smb + (st) * 64512;                                         \
        uint32_t aB = aA + 9216;                                                  \
        {                                                                         \
            int r_ = tid >> 3, c8_ = (tid & 7) * 8;                               \
            long gr_ = m0 + r_;                                                   \
            bool v_ = gr_ < N_NODES;                                              \
            cp16(aA + (r_ * LDSW + c8_) * 2,                                      \
                 As_ + (v_ ? gr_ * 128 + kc_ + c8_ : 0), v_);                     \
        }                                                                         \
        _Pragma("unroll")                                                         \
        for (int i_ = 0; i_ < 6; i_++) {                                          \
            int cc_ = tid + i_ * 512;                                             \
            int r_ = cc_ >> 3, c8_ = (cc_ & 7) * 8;                               \
            cp16(aB + (r_ * LDSW + c8_) * 2,                                      \
                 Bs_ + (long)r_ * 128 + kc_ + c8_, true);                         \
        }                                                                         \
        cp_commit();                                                              \
    }

    GLOAD(0, 0);
    const int arow = mwarp * 32 + (lane & 15);
    const int brow = nwarp * 16 + (lane & 15);
    const int acol = (lane >> 4) * 8;

#pragma unroll 1
    for (int t = 0; t < 4; t++) {
        if (t < 3) { GLOAD((t + 1) & 1, t + 1); }
        if (t < 3) asm volatile("cp.async.wait_group 1;");
        else       asm volatile("cp.async.wait_group 0;");
        __syncthreads();
        int ph = t >> 1;
        uint32_t sA = smb + (t & 1) * 64512;
        uint32_t sB = sA + 9216;
#pragma unroll
        for (int ks = 0; ks < 4; ks++) {
            int k0 = ks * 16;
            uint32_t af[2][4];
#pragma unroll
            for (int i = 0; i < 2; i++)
                ldmx4(af[i], sA + ((arow + i * 16) * LDSW + k0 + acol) * 2);
#pragma unroll
            for (int sb = 0; sb < 3; sb++) {
                const int lb = (ph == 0) ? sb : (sb == 2 ? 3 : sb);
                uint32_t bt[4];
                ldmx4(bt, sB + ((sb * 128 + brow) * LDSW + k0 + acol) * 2);
#pragma unroll
                for (int i = 0; i < 2; i++) {
                    mma16816(acc[i][lb][0], af[i], bt[0], bt[2]);
                    mma16816(acc[i][lb][1], af[i], bt[1], bt[3]);
                }
            }
        }
        __syncthreads();
    }

    // GRU epilogue: h pulled from the still-live smem A-tiles (fp16 state)
    const int r_in = lane >> 2;
    const int cpair = (lane & 3) * 2;
#pragma unroll
    for (int i = 0; i < 2; i++) {
#pragma unroll
        for (int hrow = 0; hrow < 2; hrow++) {
            int rl = mwarp * 32 + i * 16 + r_in + hrow * 8;
            long gm = m0 + rl;
            if (gm >= N_NODES) continue;
#pragma unroll
            for (int j = 0; j < 2; j++) {
                int c = nwarp * 16 + j * 8 + cpair;
                char* tile = smraw + ((c & 64) ? 64512 : 0);
                __half2 hv = *(__half2*)(tile + (rl * LDSW + (c & 63)) * 2);
                float2 hf = __half22float2(hv);
                float g2[2];
#pragma unroll
                for (int e = 0; e < 2; e++) {
                    int cc = c + e;
                    float rs = acc[i][0][j][hrow * 2 + e] + b_ih[cc] + b_hh[cc];
                    float zs = acc[i][1][j][hrow * 2 + e] + b_ih[128 + cc] + b_hh[128 + cc];
                    float in_ = acc[i][2][j][hrow * 2 + e] + b_ih[256 + cc];
                    float hn  = acc[i][3][j][hrow * 2 + e] + b_hh[256 + cc];
                    float r = sigm(rs), z = sigm(zs);
                    float n = tanhf(in_ + r * hn);
                    g2[e] = (1.f - z) * n + z * ((e == 0) ? hf.x : hf.y);
                }
                *(__half2*)&gh[gm * 128 + c] = __floats2half2_rn(g2[0], g2[1]);
            }
        }
    }
#undef GLOAD
}

// ---------------- GCN aggregation (pull-CSR, warp/node) ----------------
__global__ void k_gcn_agg(const float* __restrict__ bias) {
    int v = blockIdx.x * 8 + (threadIdx.x >> 5);
    if (v >= N_NODES) return;
    int lane = threadIdx.x & 31;
    const uint2* x2 = (const uint2*)d_XWh;
    float4 acc = make_float4(0.f, 0.f, 0.f, 0.f);
    float dv = d_dinv[v];
    int s = d_off[v], e = d_off[v + 1];
    for (int i = s; i < e; i++) {
        int u = d_csr[i];
        float c = d_dinv[u] * dv;
        float4 t = h4tof4(x2[(long)u * 32 + lane]);
        acc.x += t.x * c; acc.y += t.y * c; acc.z += t.z * c; acc.w += t.w * c;
    }
    float4 slf = h4tof4(x2[(long)v * 32 + lane]);
    float sc = dv * dv;
    float4 b = ((const float4*)bias)[lane];
    acc.x = leaky(acc.x + slf.x * sc + b.x);
    acc.y = leaky(acc.y + slf.y * sc + b.y);
    acc.z = leaky(acc.z + slf.z * sc + b.z);
    acc.w = leaky(acc.w + slf.w * sc + b.w);
    uint32_t hi, lo = pack4(acc.x, acc.y, acc.z, acc.w, &hi);
    uint2 pk = make_uint2(lo, hi);
    ((uint2*)d_Hbh)[(long)v * 32 + lane] = pk;
    ((uint2*)d_gh)[(long)v * 32 + lane] = pk;
}

// ---------------- gather (pull-CSR, warp/node) ----------------
__global__ void k_gg_agg() {
    int v = blockIdx.x * 8 + (threadIdx.x >> 5);
    if (v >= N_NODES) return;
    int lane = threadIdx.x & 31;
    const uint2* g2 = (const uint2*)d_gh;
    float4 acc = make_float4(0.f, 0.f, 0.f, 0.f);
    int s = d_off[v], e = d_off[v + 1];
    for (int i = s; i < e; i++) {
        int u = d_csr[i];
        float4 t = h4tof4(g2[(long)u * 32 + lane]);
        acc.x += t.x; acc.y += t.y; acc.z += t.z; acc.w += t.w;
    }
    uint32_t hi, lo = pack4(acc.x, acc.y, acc.z, acc.w, &hi);
    ((uint2*)d_mh)[(long)v * 32 + lane] = make_uint2(lo, hi);
}

// ---------------- elementwise (fp16 in, fp16 out) ----------------
__global__ void k_resid() {
    long idx = (long)blockIdx.x * 256 + threadIdx.x;
    if (idx >= 1600000L) return;
    float4 g = h4tof4(((const uint2*)d_gh)[idx]);
    float4 hh = h4tof4(((const uint2*)d_Hbh)[idx]);
    uint32_t hi, lo = pack4(leaky(g.x) + hh.x, leaky(g.y) + hh.y,
                            leaky(g.z) + hh.z, leaky(g.w) + hh.w, &hi);
    ((uint2*)d_hh)[idx] = make_uint2(lo, hi);
}

// ---------------- merged loss ----------------
__global__ void k_loss(const int* __restrict__ row, const int* __restrict__ col,
                       const int* __restrict__ batch, float* __restrict__ out) {
    __shared__ float sm[NGRAPH];
    if (threadIdx.x < NGRAPH) sm[threadIdx.x] = 0.f;
    __syncthreads();
    if (blockIdx.x < 512) {
        for (int v = blockIdx.x * 256 + threadIdx.x; v < N_NODES; v += 512 * 256)
            atomicAdd(&sm[batch[v]], -0.5f * d_probs[v] * (float)d_degr[v]);
    } else {
        for (int e = (blockIdx.x - 512) * 256 + threadIdx.x; e < N_EDGES; e += 512 * 256) {
            int r = row[e];
            atomicAdd(&sm[batch[r]], 0.5f * d_probs[r] * d_probs[col[e]]);
        }
    }
    __syncthreads();
    if (threadIdx.x < NGRAPH) atomicAdd(&out[threadIdx.x], sm[threadIdx.x]);
}

// ---------------- launch ----------------
extern "C" void kernel_launch(void* const* d_in, const int* in_sizes, int n_in,
                              void* d_out, int out_size)
{
    const float* x     = (const float*)d_in[0];
    const int*   ei    = (const int*)d_in[1];
    const int*   batch = (const int*)d_in[2];
    const float* W_gcn = (const float*)d_in[3];
    const float* b_gcn = (const float*)d_in[4];
    const float* W_gg  = (const float*)d_in[5];
    const float* W_ih  = (const float*)d_in[6];
    const float* W_hh  = (const float*)d_in[7];
    const float* b_ih  = (const float*)d_in[8];
    const float* b_hh  = (const float*)d_in[9];
    const float* W1    = (const float*)d_in[10];
    const float* b1    = (const float*)d_in[11];
    const float* W2    = (const float*)d_in[12];
    const float* b2    = (const float*)d_in[13];
    float* out = (float*)d_out;
    const int* row = ei;
    const int* col = ei + N_EDGES;

    const int SMEM = 2 * 36864;    // k_mm double buffer
    const int SMG  = 2 * 64512;    // k_gates double buffer (129 KB)
    cudaFuncSetAttribute(k_mm<0>, cudaFuncAttributeMaxDynamicSharedMemorySize, SMEM);
    cudaFuncSetAttribute(k_mm<2>, cudaFuncAttributeMaxDynamicSharedMemorySize, SMEM);
    cudaFuncSetAttribute(k_gates, cudaFuncAttributeMaxDynamicSharedMemorySize, SMG);

    __half *xh, *gh, *mh, *hh, *wh, *XWh;
    cudaGetSymbolAddress((void**)&xh, d_xh);
    cudaGetSymbolAddress((void**)&gh, d_gh);
    cudaGetSymbolAddress((void**)&mh, d_mh);
    cudaGetSymbolAddress((void**)&hh, d_hh);
    cudaGetSymbolAddress((void**)&wh, d_wh);
    cudaGetSymbolAddress((void**)&XWh, d_XWh);

    // prep + CSR build
    k_prep<<<6766, 256>>>(x, W_gcn, W_hh, W1, out);
    k_count<<<3125, 256>>>(row, col);
    k_wc<<<1152, 128>>>(W_gg, W_ih);
    k_scan1<<<196, 256>>>();
    k_scan2<<<1, 256>>>();
    k_scan3<<<196, 256>>>();
    k_scatter<<<3125, 256>>>(row, col);

    // GCN
    k_mm<0><<<MTILES, 256, SMEM>>>(xh, wh, nullptr, nullptr, XWh);
    k_gcn_agg<<<6250, 256>>>(b_gcn);

    // 3x GatedGraphConv (gather -> gates GEMM + GRU; fp16 state in gh)
    for (int l = 0; l < 3; l++) {
        k_gg_agg<<<6250, 256>>>();
        k_gates<<<782, 512, SMG>>>(mh, gh, wh + (long)(128 + l * 384) * 128,
                                   wh + 1280L * 128, b_ih, b_hh);
    }

    // head (GEMM + W1/b1 + leaky + W2/b2 + sigmoid fused -> d_probs)
    k_resid<<<6250, 256>>>();
    k_mm<2><<<MTILES, 256, SMEM>>>(hh, wh + 1664L * 128, b1, b2, (void*)W2);

    // loss
    k_loss<<<1024, 256>>>(row, col, batch, out);
}

// round 17
// speedup vs baseline: 1.1947x; 1.0236x over previous
#include <cuda_runtime.h>
#include <cuda_fp16.h>
#include <math.h>
#include <stdint.h>

#define N_NODES 50000
#define N_EDGES 800000
#define NGRAPH  64
#define NEG     0.01f
#define MTILES  391   // ceil(50000/128)
#define LDSW    72    // padded smem row stride (half) = 144B

// ---------------- device globals ----------------
__device__ __half d_Hbh[6400000];    // residual h (fp16)
__device__ __half d_xh[6400000];     // x quantized
__device__ __half d_gh[6400000];     // g state (fp16, in-place per layer)
__device__ __half d_mh[6400000];     // aggregated message
__device__ __half d_hh[6400000];     // resid output (head GEMM A)
__device__ __half d_XWh[6400000];    // GCN xw (fp16, gathered)
// weight rows [n][k]: 0..127 Wgcn^T | 128+l*384 Wc[l]=Wgg[l]@WihT | 1280..1663 Whh | 1664..1791 W1^T
__device__ __half d_wh[229376];
__device__ float d_dinv[N_NODES];
__device__ float d_probs[N_NODES];
__device__ int d_degc[N_NODES];
__device__ int d_fill[N_NODES];
__device__ int d_off[N_NODES + 1];
__device__ int d_csr[N_EDGES];
__device__ int d_bsum[256];

__device__ __forceinline__ float leaky(float x) { return x > 0.f ? x : NEG * x; }
__device__ __forceinline__ float sigm(float x)  { return 1.f / (1.f + __expf(-x)); }

__device__ __forceinline__ uint32_t smem_u32(const void* p) {
    uint32_t a;
    asm("{ .reg .u64 t; cvta.to.shared.u64 t, %1; cvt.u32.u64 %0, t; }" : "=r"(a) : "l"(p));
    return a;
}
__device__ __forceinline__ void cp16(uint32_t dst, const void* src, bool valid) {
    int sz = valid ? 16 : 0;
    asm volatile("cp.async.cg.shared.global [%0], [%1], 16, %2;"
                 :: "r"(dst), "l"(src), "r"(sz));
}
__device__ __forceinline__ void cp_commit() { asm volatile("cp.async.commit_group;"); }
__device__ __forceinline__ void ldmx4(uint32_t* r, uint32_t addr) {
    asm volatile("ldmatrix.sync.aligned.m8n8.x4.shared.b16 {%0,%1,%2,%3}, [%4];"
                 : "=r"(r[0]), "=r"(r[1]), "=r"(r[2]), "=r"(r[3]) : "r"(addr));
}
__device__ __forceinline__ void mma16816(float* c, const uint32_t* a, uint32_t b0, uint32_t b1) {
    asm volatile(
        "mma.sync.aligned.m16n8k16.row.col.f32.f16.f16.f32 "
        "{%0,%1,%2,%3}, {%4,%5,%6,%7}, {%8,%9}, {%0,%1,%2,%3};"
        : "+f"(c[0]), "+f"(c[1]), "+f"(c[2]), "+f"(c[3])
        : "r"(a[0]), "r"(a[1]), "r"(a[2]), "r"(a[3]), "r"(b0), "r"(b1));
}
__device__ __forceinline__ uint32_t pack4(float a, float b, float c, float d, uint32_t* hi) {
    __half2 h0 = __floats2half2_rn(a, b);
    __half2 h1 = __floats2half2_rn(c, d);
    *hi = *(uint32_t*)&h1;
    return *(uint32_t*)&h0;
}
__device__ __forceinline__ float4 h4tof4(uint2 p) {
    __half2 a = *(__half2*)&p.x, b = *(__half2*)&p.y;
    float2 fa = __half22float2(a), fb = __half22float2(b);
    return make_float4(fa.x, fa.y, fb.x, fb.y);
}
// accumulate 8 halves (uint4) scaled by c into a[8]
__device__ __forceinline__ void h8acc(uint4 p, float c, float* a) {
    const __half2* h = (const __half2*)&p;
#pragma unroll
    for (int q = 0; q < 4; q++) {
        float2 f = __half22float2(h[q]);
        a[q * 2]     += f.x * c;
        a[q * 2 + 1] += f.y * c;
    }
}
__device__ __forceinline__ uint4 pack8(const float* a) {
    uint4 r;
    __half2 h0 = __floats2half2_rn(a[0], a[1]);
    __half2 h1 = __floats2half2_rn(a[2], a[3]);
    __half2 h2 = __floats2half2_rn(a[4], a[5]);
    __half2 h3 = __floats2half2_rn(a[6], a[7]);
    r.x = *(uint32_t*)&h0; r.y = *(uint32_t*)&h1;
    r.z = *(uint32_t*)&h2; r.w = *(uint32_t*)&h3;
    return r;
}

// ---------------- merged prep: quant_x | zero | wq ----------------
__global__ void k_prep(const float* __restrict__ x, const float* __restrict__ Wgcn,
                       const float* __restrict__ Whh, const float* __restrict__ W1,
                       float* __restrict__ out) {
    int b = blockIdx.x, tid = threadIdx.x;
    if (b < 6250) {
        long idx = (long)b * 256 + tid;
        if (idx < 1600000L) {
            float4 v = ((const float4*)x)[idx];
            uint32_t hi, lo = pack4(v.x, v.y, v.z, v.w, &hi);
            ((uint2*)d_xh)[idx] = make_uint2(lo, hi);
        }
    } else if (b < 6446) {
        int i = (b - 6250) * 256 + tid;
        if (i < N_NODES) { d_degc[i] = 0; d_fill[i] = 0; }
        if (i < NGRAPH) out[i] = 0.f;
    } else {
        int idx = (b - 6446) * 256 + tid;
        if (idx < 640 * 128) {
            int r = idx >> 7, k = idx & 127;
            float v; long dr;
            if (r < 128)      { v = Wgcn[k * 128 + r];        dr = r; }
            else if (r < 512) { int n = r - 128; v = Whh[n * 128 + k]; dr = 1280 + n; }
            else              { int n = r - 512; v = W1[k * 128 + n];  dr = 1664 + n; }
            d_wh[dr * 128 + k] = __float2half_rn(v);
        }
    }
}
// Wc[l][j][n] = sum_c Wgg[l][j][c] * Wih[n][c]
__global__ void k_wc(const float* __restrict__ Wgg, const float* __restrict__ Wih) {
    int b = blockIdx.x;            // 0..1151
    int l = b / 384, n = b % 384;
    __shared__ float s[128];
    s[threadIdx.x] = Wih[n * 128 + threadIdx.x];
    __syncthreads();
    const float* wg = Wgg + (long)l * 16384 + threadIdx.x * 128;
    float acc = 0.f;
#pragma unroll 8
    for (int c = 0; c < 128; c++) acc += wg[c] * s[c];
    d_wh[(long)(128 + l * 384 + n) * 128 + threadIdx.x] = __float2half_rn(acc);
}

// ---------------- CSR build ----------------
__global__ void k_count(const int* __restrict__ col) {
    int e = blockIdx.x * blockDim.x + threadIdx.x;
    if (e < N_EDGES) atomicAdd(&d_degc[col[e]], 1);
}
__global__ void k_scan1() {     // + dinv
    __shared__ int sm[256];
    int i = blockIdx.x * 256 + threadIdx.x;
    int v = (i < N_NODES) ? d_degc[i] : 0;
    if (i < N_NODES) d_dinv[i] = rsqrtf((float)v + 1.f);
    sm[threadIdx.x] = v;
    __syncthreads();
    for (int o = 128; o; o >>= 1) {
        if (threadIdx.x < o) sm[threadIdx.x] += sm[threadIdx.x + o];
        __syncthreads();
    }
    if (threadIdx.x == 0) d_bsum[blockIdx.x] = sm[0];
}
__global__ void k_scan2() {
    __shared__ int sm[256];
    int t = threadIdx.x;
    int v = (t < 196) ? d_bsum[t] : 0;
    sm[t] = v; __syncthreads();
    for (int o = 1; o < 256; o <<= 1) {
        int x = (t >= o) ? sm[t - o] : 0;
        __syncthreads(); sm[t] += x; __syncthreads();
    }
    if (t < 196) d_bsum[t] = sm[t] - v;
    if (t == 0) d_off[N_NODES] = N_EDGES;
}
__global__ void k_scan3() {
    __shared__ int sm[256];
    int t = threadIdx.x, i = blockIdx.x * 256 + t;
    int v = (i < N_NODES) ? d_degc[i] : 0;
    sm[t] = v; __syncthreads();
    for (int o = 1; o < 256; o <<= 1) {
        int x = (t >= o) ? sm[t - o] : 0;
        __syncthreads(); sm[t] += x; __syncthreads();
    }
    if (i < N_NODES) d_off[i] = d_bsum[blockIdx.x] + sm[t] - v;
}
__global__ void k_scatter(const int* __restrict__ row, const int* __restrict__ col) {
    int e = blockIdx.x * blockDim.x + threadIdx.x;
    if (e < N_EDGES) {
        int c = col[e];
        d_csr[d_off[c] + atomicAdd(&d_fill[c], 1)] = row[e];
    }
}

// ---------------- fp16 HMMA GEMM, K=128 ----------------
// EPI 0: half out.  EPI 2: fused head -> probs (bias=b1, W2 in Cv, +b2, sigmoid).
template <int EPI>
__global__ void __launch_bounds__(256) k_mm(
    const __half* __restrict__ A, const __half* __restrict__ B,
    const float* __restrict__ bias, const float* __restrict__ b2,
    void* __restrict__ Cv)
{
    extern __shared__ __align__(16) char smraw[];
    __shared__ float srow[128];
    uint32_t smb = smem_u32(smraw);
    const int tid = threadIdx.x, lane = tid & 31, wid = tid >> 5;
    const int mw = (wid >> 1) * 32;
    const int nw = (wid & 1) * 64;
    const long m0 = (long)blockIdx.x * 128;

    if (EPI == 2) {
        if (tid < 128) srow[tid] = 0.f;
    }

    float acc[2][8][4];
#pragma unroll
    for (int i = 0; i < 2; i++)
#pragma unroll
        for (int j = 0; j < 8; j++)
#pragma unroll
            for (int e = 0; e < 4; e++) acc[i][j][e] = 0.f;

#define LOAD_STAGE(st, kc)                                                        \
    {                                                                             \
        uint32_t aA = smb + (st) * 36864;                                         \
        uint32_t aB = aA + 18432;                                                 \
        _Pragma("unroll")                                                         \
        for (int i_ = 0; i_ < 4; i_++) {                                          \
            int c_ = tid + i_ * 256;                                              \
            int row_ = c_ >> 3, col8_ = (c_ & 7) * 8;                             \
            long gr_ = m0 + row_;                                                 \
            bool v_ = gr_ < N_NODES;                                              \
            cp16(aA + (row_ * LDSW + col8_) * 2,                                  \
                 A + (v_ ? gr_ * 128 + (kc) + col8_ : 0), v_);                    \
            cp16(aB + (row_ * LDSW + col8_) * 2,                                  \
                 B + (long)row_ * 128 + (kc) + col8_, true);                      \
        }                                                                         \
        cp_commit();                                                              \
    }

    LOAD_STAGE(0, 0);
    const int arow = mw + (lane & 15);
    const int brow = nw + (lane & 15);
    const int acol = (lane >> 4) * 8;

#pragma unroll 1
    for (int ch = 0; ch < 2; ch++) {
        if (ch < 1) { LOAD_STAGE(1, 64); }
        if (ch < 1) asm volatile("cp.async.wait_group 1;");
        else        asm volatile("cp.async.wait_group 0;");
        __syncthreads();
        uint32_t sA = smb + (ch & 1) * 36864;
        uint32_t sB = sA + 18432;
#pragma unroll
        for (int ks = 0; ks < 4; ks++) {
            int k0 = ks * 16;
            uint32_t af[2][4];
#pragma unroll
            for (int i = 0; i < 2; i++)
                ldmx4(af[i], sA + ((arow + i * 16) * LDSW + k0 + acol) * 2);
#pragma unroll
            for (int j2 = 0; j2 < 4; j2++) {
                uint32_t t[4];
                ldmx4(t, sB + ((brow + j2 * 16) * LDSW + k0 + acol) * 2);
#pragma unroll
                for (int i = 0; i < 2; i++) {
                    mma16816(acc[i][2 * j2],     af[i], t[0], t[2]);
                    mma16816(acc[i][2 * j2 + 1], af[i], t[1], t[3]);
                }
            }
        }
        __syncthreads();
    }

    const int r_in = lane >> 2;
    const int cpair = (lane & 3) * 2;
    if (EPI == 0) {
#pragma unroll
        for (int i = 0; i < 2; i++) {
            long gm = m0 + mw + i * 16 + r_in;
#pragma unroll
            for (int j = 0; j < 8; j++) {
                int colg = nw + j * 8 + cpair;
                __half* C = (__half*)Cv;
                __half2 h0 = __floats2half2_rn(acc[i][j][0], acc[i][j][1]);
                __half2 h1 = __floats2half2_rn(acc[i][j][2], acc[i][j][3]);
                if (gm < N_NODES)     *(__half2*)&C[gm * 128 + colg] = h0;
                if (gm + 8 < N_NODES) *(__half2*)&C[(gm + 8) * 128 + colg] = h1;
            }
        }
    } else {
        const float* W2 = (const float*)Cv;
#pragma unroll
        for (int i = 0; i < 2; i++) {
            float p0 = 0.f, p1 = 0.f;
#pragma unroll
            for (int j = 0; j < 8; j++) {
                int colg = nw + j * 8 + cpair;
                float w0 = W2[colg], w1 = W2[colg + 1];
                float bx = bias[colg], by = bias[colg + 1];
                p0 += leaky(acc[i][j][0] + bx) * w0 + leaky(acc[i][j][1] + by) * w1;
                p1 += leaky(acc[i][j][2] + bx) * w0 + leaky(acc[i][j][3] + by) * w1;
            }
            atomicAdd(&srow[mw + i * 16 + r_in], p0);
            atomicAdd(&srow[mw + i * 16 + r_in + 8], p1);
        }
        __syncthreads();
        if (tid < 128) {
            long gm = m0 + tid;
            if (gm < N_NODES) d_probs[gm] = sigm(srow[tid] + b2[0]);
        }
    }
#undef LOAD_STAGE
}

// ---------------- fused gates GEMM + GRU (2-stage; h read from live smem A-tiles) ----------------
// Blocks: 0=r_sum, 1=z_sum, 2=i_n, 3=h_n.
// chunks 0-1: A=mh, B=Wc[l] -> {0,1,2};  chunks 2-3: A=gh, B=Whh -> {0,1,3}
// After the loop: stage0 A-tile = gh cols 0-63, stage1 A-tile = gh cols 64-127.
__global__ void __launch_bounds__(512) k_gates(
    const __half* __restrict__ mh, __half* gh,
    const __half* __restrict__ wc, const __half* __restrict__ whh,
    const float* __restrict__ b_ih, const float* __restrict__ b_hh)
{
    extern __shared__ __align__(16) char smraw[];
    uint32_t smb = smem_u32(smraw);
    const int tid = threadIdx.x, lane = tid & 31, w = tid >> 5;
    const int mwarp = w & 1;
    const int nwarp = w >> 1;
    const long m0 = (long)blockIdx.x * 64;

    float acc[2][4][2][4];
#pragma unroll
    for (int i = 0; i < 2; i++)
#pragma unroll
        for (int b = 0; b < 4; b++)
#pragma unroll
            for (int j = 0; j < 2; j++)
#pragma unroll
                for (int e = 0; e < 4; e++) acc[i][b][j][e] = 0.f;

#define GLOAD(st, c)                                                              \
    {                                                                             \
        int p_ = (c) >> 1, kc_ = ((c) & 1) * 64;                                  \
        const __half* As_ = p_ ? gh : mh;                                         \
        const __half* Bs_ = p_ ? whh : wc;                                        \
        uint32_t aA = smb + (st) * 64512;                                         \
        uint32_t aB = aA + 9216;                                                  \
        {                                                                         \
            int r_ = tid >> 3, c8_ = (tid & 7) * 8;                               \
            long gr_ = m0 + r_;                                                   \
            bool v_ = gr_ < N_NODES;                                              \
            cp16(aA + (r_ * LDSW + c8_) * 2,                                      \
                 As_ + (v_ ? gr_ * 128 + kc_ + c8_ : 0), v_);                     \
        }                                                                         \
        _Pragma("unroll")                                                         \
        for (int i_ = 0; i_ < 6; i_++) {                                          \
            int cc_ = tid + i_ * 512;                                             \
            int r_ = cc_ >> 3, c8_ = (cc_ & 7) * 8;                               \
            cp16(aB + (r_ * LDSW + c8_) * 2,                                      \
                 Bs_ + (long)r_ * 128 + kc_ + c8_, true);                         \
        }                                                                         \
        cp_commit();                                                              \
    }

    GLOAD(0, 0);
    const int arow = mwarp * 32 + (lane & 15);
    const int brow = nwarp * 16 + (lane & 15);
    const int acol = (lane >> 4) * 8;

#pragma unroll 1
    for (int t = 0; t < 4; t++) {
        if (t < 3) { GLOAD((t + 1) & 1, t + 1); }
        if (t < 3) asm volatile("cp.async.wait_group 1;");
        else       asm volatile("cp.async.wait_group 0;");
        __syncthreads();
        int ph = t >> 1;
        uint32_t sA = smb + (t & 1) * 64512;
        uint32_t sB = sA + 9216;
#pragma unroll
        for (int ks = 0; ks < 4; ks++) {
            int k0 = ks * 16;
            uint32_t af[2][4];
#pragma unroll
            for (int i = 0; i < 2; i++)
                ldmx4(af[i], sA + ((arow + i * 16) * LDSW + k0 + acol) * 2);
#pragma unroll
            for (int sb = 0; sb < 3; sb++) {
                const int lb = (ph == 0) ? sb : (sb == 2 ? 3 : sb);
                uint32_t bt[4];
                ldmx4(bt, sB + ((sb * 128 + brow) * LDSW + k0 + acol) * 2);
#pragma unroll
                for (int i = 0; i < 2; i++) {
                    mma16816(acc[i][lb][0], af[i], bt[0], bt[2]);
                    mma16816(acc[i][lb][1], af[i], bt[1], bt[3]);
                }
            }
        }
        __syncthreads();
    }

    // GRU epilogue: h pulled from the still-live smem A-tiles (fp16 state)
    const int r_in = lane >> 2;
    const int cpair = (lane & 3) * 2;
#pragma unroll
    for (int i = 0; i < 2; i++) {
#pragma unroll
        for (int hrow = 0; hrow < 2; hrow++) {
            int rl = mwarp * 32 + i * 16 + r_in + hrow * 8;
            long gm = m0 + rl;
            if (gm >= N_NODES) continue;
#pragma unroll
            for (int j = 0; j < 2; j++) {
                int c = nwarp * 16 + j * 8 + cpair;
                char* tile = smraw + ((c & 64) ? 64512 : 0);
                __half2 hv = *(__half2*)(tile + (rl * LDSW + (c & 63)) * 2);
                float2 hf = __half22float2(hv);
                float g2[2];
#pragma unroll
                for (int e = 0; e < 2; e++) {
                    int cc = c + e;
                    float rs = acc[i][0][j][hrow * 2 + e] + b_ih[cc] + b_hh[cc];
                    float zs = acc[i][1][j][hrow * 2 + e] + b_ih[128 + cc] + b_hh[128 + cc];
                    float in_ = acc[i][2][j][hrow * 2 + e] + b_ih[256 + cc];
                    float hn  = acc[i][3][j][hrow * 2 + e] + b_hh[256 + cc];
                    float r = sigm(rs), z = sigm(zs);
                    float n = tanhf(in_ + r * hn);
                    g2[e] = (1.f - z) * n + z * ((e == 0) ? hf.x : hf.y);
                }
                *(__half2*)&gh[gm * 128 + c] = __floats2half2_rn(g2[0], g2[1]);
            }
        }
    }
#undef GLOAD
}

// ---------------- GCN aggregation (pull-CSR, 2 nodes/warp, uint4 lanes) ----------------
__global__ void k_gcn_agg(const float* __restrict__ bias) {
    int v = blockIdx.x * 16 + (threadIdx.x >> 4);
    if (v >= N_NODES) return;
    int l16 = threadIdx.x & 15;
    const uint4* x4 = (const uint4*)d_XWh;    // node row = 16 uint4
    float a[8] = {0.f, 0.f, 0.f, 0.f, 0.f, 0.f, 0.f, 0.f};
    float dv = d_dinv[v];
    int s = d_off[v], e = d_off[v + 1];
    for (int i = s; i < e; i++) {
        int u = d_csr[i];
        h8acc(x4[(long)u * 16 + l16], d_dinv[u] * dv, a);
    }
    h8acc(x4[(long)v * 16 + l16], dv * dv, a);
    const float4* b4 = (const float4*)bias;
    float4 b0 = b4[l16 * 2], b1 = b4[l16 * 2 + 1];
    a[0] = leaky(a[0] + b0.x); a[1] = leaky(a[1] + b0.y);
    a[2] = leaky(a[2] + b0.z); a[3] = leaky(a[3] + b0.w);
    a[4] = leaky(a[4] + b1.x); a[5] = leaky(a[5] + b1.y);
    a[6] = leaky(a[6] + b1.z); a[7] = leaky(a[7] + b1.w);
    uint4 pk = pack8(a);
    ((uint4*)d_Hbh)[(long)v * 16 + l16] = pk;
    ((uint4*)d_gh)[(long)v * 16 + l16] = pk;
}

// ---------------- gather (pull-CSR, 2 nodes/warp, uint4 lanes) ----------------
__global__ void k_gg_agg() {
    int v = blockIdx.x * 16 + (threadIdx.x >> 4);
    if (v >= N_NODES) return;
    int l16 = threadIdx.x & 15;
    const uint4* g4 = (const uint4*)d_gh;
    float a[8] = {0.f, 0.f, 0.f, 0.f, 0.f, 0.f, 0.f, 0.f};
    int s = d_off[v], e = d_off[v + 1];
    for (int i = s; i < e; i++) {
        int u = d_csr[i];
        h8acc(g4[(long)u * 16 + l16], 1.f, a);
    }
    ((uint4*)d_mh)[(long)v * 16 + l16] = pack8(a);
}

// ---------------- elementwise (fp16 in, fp16 out) ----------------
__global__ void k_resid() {
    long idx = (long)blockIdx.x * 256 + threadIdx.x;
    if (idx >= 1600000L) return;
    float4 g = h4tof4(((const uint2*)d_gh)[idx]);
    float4 hh = h4tof4(((const uint2*)d_Hbh)[idx]);
    uint32_t hi, lo = pack4(leaky(g.x) + hh.x, leaky(g.y) + hh.y,
                            leaky(g.z) + hh.z, leaky(g.w) + hh.w, &hi);
    ((uint2*)d_hh)[idx] = make_uint2(lo, hi);
}

// ---------------- loss (edge-only: 0.5*p_r*(p_c - 1) binned by batch[r]) ----------------
__global__ void k_loss(const int* __restrict__ row, const int* __restrict__ col,
                       const int* __restrict__ batch, float* __restrict__ out) {
    __shared__ float sm[NGRAPH];
    if (threadIdx.x < NGRAPH) sm[threadIdx.x] = 0.f;
    __syncthreads();
    for (int e = blockIdx.x * 256 + threadIdx.x; e < N_EDGES; e += gridDim.x * 256) {
        int r = row[e];
        atomicAdd(&sm[batch[r]], 0.5f * d_probs[r] * (d_probs[col[e]] - 1.f));
    }
    __syncthreads();
    if (threadIdx.x < NGRAPH) atomicAdd(&out[threadIdx.x], sm[threadIdx.x]);
}

// ---------------- launch ----------------
extern "C" void kernel_launch(void* const* d_in, const int* in_sizes, int n_in,
                              void* d_out, int out_size)
{
    const float* x     = (const float*)d_in[0];
    const int*   ei    = (const int*)d_in[1];
    const int*   batch = (const int*)d_in[2];
    const float* W_gcn = (const float*)d_in[3];
    const float* b_gcn = (const float*)d_in[4];
    const float* W_gg  = (const float*)d_in[5];
    const float* W_ih  = (const float*)d_in[6];
    const float* W_hh  = (const float*)d_in[7];
    const float* b_ih  = (const float*)d_in[8];
    const float* b_hh  = (const float*)d_in[9];
    const float* W1    = (const float*)d_in[10];
    const float* b1    = (const float*)d_in[11];
    const float* W2    = (const float*)d_in[12];
    const float* b2    = (const float*)d_in[13];
    float* out = (float*)d_out;
    const int* row = ei;
    const int* col = ei + N_EDGES;

    const int SMEM = 2 * 36864;    // k_mm double buffer
    const int SMG  = 2 * 64512;    // k_gates double buffer (129 KB)
    cudaFuncSetAttribute(k_mm<0>, cudaFuncAttributeMaxDynamicSharedMemorySize, SMEM);
    cudaFuncSetAttribute(k_mm<2>, cudaFuncAttributeMaxDynamicSharedMemorySize, SMEM);
    cudaFuncSetAttribute(k_gates, cudaFuncAttributeMaxDynamicSharedMemorySize, SMG);

    __half *xh, *gh, *mh, *hh, *wh, *XWh;
    cudaGetSymbolAddress((void**)&xh, d_xh);
    cudaGetSymbolAddress((void**)&gh, d_gh);
    cudaGetSymbolAddress((void**)&mh, d_mh);
    cudaGetSymbolAddress((void**)&hh, d_hh);
    cudaGetSymbolAddress((void**)&wh, d_wh);
    cudaGetSymbolAddress((void**)&XWh, d_XWh);

    // prep + CSR build
    k_prep<<<6766, 256>>>(x, W_gcn, W_hh, W1, out);
    k_count<<<3125, 256>>>(col);
    k_wc<<<1152, 128>>>(W_gg, W_ih);
    k_scan1<<<196, 256>>>();
    k_scan2<<<1, 256>>>();
    k_scan3<<<196, 256>>>();
    k_scatter<<<3125, 256>>>(row, col);

    // GCN
    k_mm<0><<<MTILES, 256, SMEM>>>(xh, wh, nullptr, nullptr, XWh);
    k_gcn_agg<<<3125, 256>>>(b_gcn);

    // 3x GatedGraphConv (gather -> gates GEMM + GRU; fp16 state in gh)
    for (int l = 0; l < 3; l++) {
        k_gg_agg<<<3125, 256>>>();
        k_gates<<<782, 512, SMG>>>(mh, gh, wh + (long)(128 + l * 384) * 128,
                                   wh + 1280L * 128, b_ih, b_hh);
    }

    // head (GEMM + W1/b1 + leaky + W2/b2 + sigmoid fused -> d_probs)
    k_resid<<<6250, 256>>>();
    k_mm<2><<<MTILES, 256, SMEM>>>(hh, wh + 1664L * 128, b1, b2, (void*)W2);

    // loss
    k_loss<<<512, 256>>>(row, col, batch, out);
}